// round 3
// baseline (speedup 1.0000x reference)
#include <cuda_runtime.h>
#include <cstdint>

// VectorQuantStraightThrough: z_e [32,4096,64] f32, emb [512,64] f32
// d2 = fl( fl( ||z||^2 - fl(2*z.e) ) + ||e||^2 )  (replicates reference fp32
// rounding; per-row-constant z2 errors are argmin-invariant).
// Two-kernel: (A) per-half-codebook argmin partials, (B) merge + gather.

#define NROWS   (32 * 4096)   // 131072
#define DDIM    64
#define KCB     512
#define KHALF   256
#define TPB     256
#define ROWTILE 256           // rows per CTA in kernel A (1 row/thread)
#define NTILES  (NROWS / ROWTILE)   // 512
#define GRID_A  (NTILES * 2)        // 1024 (x2 codebook halves)

// scratch: [half][row] = (best_d, best_global_idx as float)
__device__ float2 g_part[2][NROWS];

// packed f32x2 helpers (Blackwell sm_103a)
#define FFMA2(acc, a, b) \
    asm("fma.rn.f32x2 %0, %1, %2, %3;" : "=l"(acc) : "l"(a), "l"(b), "l"(acc))
#define FADD2(out, a, b) \
    asm("add.rn.f32x2 %0, %1, %2;" : "=l"(out) : "l"(a), "l"(b))
#define UNPACK2(lo, hi, in) \
    asm("mov.b64 {%0, %1}, %2;" : "=f"(lo), "=f"(hi) : "l"(in))

// ---------------- Kernel A: partial argmin over one codebook half ----------
__global__ __launch_bounds__(TPB, 2)
void vq_partial_kernel(const float* __restrict__ z,
                       const float* __restrict__ emb) {
    extern __shared__ float smem[];
    float* se    = smem;                 // [KHALF][DDIM]
    float* sbias = smem + KHALF * DDIM;  // [KHALF]

    const int tid  = threadIdx.x;
    const int half = blockIdx.x & 1;
    const int tile = blockIdx.x >> 1;

    // stage this half of the codebook (64 KB)
    {
        const float4* g4 = (const float4*)(emb + half * KHALF * DDIM);
        float4* s4 = (float4*)se;
        const int n4 = KHALF * DDIM / 4;  // 4096
        #pragma unroll 4
        for (int i = tid; i < n4; i += TPB) s4[i] = g4[i];
    }
    __syncthreads();

    // bias ||e_k||^2 (one k per thread; TPB == KHALF)
    {
        const float* e = se + tid * DDIM;
        float s = 0.f;
        #pragma unroll
        for (int d = 0; d < DDIM; d++) s = fmaf(e[d], e[d], s);
        sbias[tid] = s;
    }
    __syncthreads();

    // this thread's z row, packed f32x2
    const long long n = (long long)tile * ROWTILE + tid;
    unsigned long long zr[DDIM / 2];
    {
        const ulonglong2* p = (const ulonglong2*)(z + n * DDIM);
        #pragma unroll
        for (int j = 0; j < DDIM / 4; j++) {
            ulonglong2 a = p[j]; zr[2 * j] = a.x; zr[2 * j + 1] = a.y;
        }
    }

    // ||z||^2 — identical computation in both halves => consistent value
    float z2;
    {
        unsigned long long s0 = 0ull, s1 = 0ull, s2 = 0ull, s3 = 0ull;
        #pragma unroll
        for (int j = 0; j < DDIM / 4; j += 2) {
            FFMA2(s0, zr[2 * j],     zr[2 * j]);
            FFMA2(s1, zr[2 * j + 1], zr[2 * j + 1]);
            FFMA2(s2, zr[2 * j + 2], zr[2 * j + 2]);
            FFMA2(s3, zr[2 * j + 3], zr[2 * j + 3]);
        }
        FADD2(s0, s0, s1);
        FADD2(s2, s2, s3);
        FADD2(s0, s0, s2);
        float lo, hi;
        UNPACK2(lo, hi, s0);
        z2 = __fadd_rn(lo, hi);
    }

    float best = 3.4e38f;
    int   bidx = 0;

    #pragma unroll 2
    for (int k = 0; k < KHALF; k++) {
        const ulonglong2* ek = (const ulonglong2*)(se + k * DDIM);
        unsigned long long c0 = 0ull, c1 = 0ull, c2 = 0ull, c3 = 0ull;
        #pragma unroll
        for (int j = 0; j < DDIM / 4; j += 2) {
            ulonglong2 ea = ek[j];       // broadcast LDS.128
            ulonglong2 eb = ek[j + 1];
            FFMA2(c0, zr[2 * j],     ea.x);
            FFMA2(c1, zr[2 * j + 1], ea.y);
            FFMA2(c2, zr[2 * j + 2], eb.x);
            FFMA2(c3, zr[2 * j + 3], eb.y);
        }
        FADD2(c0, c0, c1);
        FADD2(c2, c2, c3);
        FADD2(c0, c0, c2);
        float lo, hi;
        UNPACK2(lo, hi, c0);
        const float dot = __fadd_rn(lo, hi);
        // reference rounding: (z2 - 2*dot) + e2, all fp32, no contraction
        const float d = __fadd_rn(__fsub_rn(z2, __fmul_rn(2.f, dot)), sbias[k]);
        if (d < best) { best = d; bidx = k; }   // strict < == first-index tiebreak
    }

    g_part[half][n] = make_float2(best, (float)(half * KHALF + bidx));
}

// ---------------- Kernel B: merge halves, gather codes, write outputs ------
// 16 threads per row; CTA covers 16 rows. Coalesced float4 stores.
#define B_ROWS_PER_CTA 16
#define GRID_B (NROWS / B_ROWS_PER_CTA)   // 8192

__global__ __launch_bounds__(TPB, 8)
void vq_merge_gather_kernel(const float* __restrict__ emb,
                            float* __restrict__ out,
                            long long out_size) {
    __shared__ int sidx[B_ROWS_PER_CTA];

    const int tid  = threadIdx.x;
    const int rloc = tid >> 4;          // 0..15 local row
    const int q    = tid & 15;          // 0..15 float4 slot within row
    const long long row0 = (long long)blockIdx.x * B_ROWS_PER_CTA;

    if (tid < B_ROWS_PER_CTA) {
        const long long n = row0 + tid;
        const float2 p0 = g_part[0][n];
        const float2 p1 = g_part[1][n];
        // first-argmin semantics: half-1 wins only on strictly smaller d
        sidx[tid] = (p1.x < p0.x) ? (int)p1.y : (int)p0.y;
    }
    __syncthreads();

    const long long n   = row0 + rloc;
    const int idx       = sidx[rloc];
    const float4 v      = ((const float4*)(emb + (long long)idx * DDIM))[q];
    const long long ND  = (long long)NROWS * DDIM;   // 8388608
    const long long off = n * DDIM + q * 4;

    if (out_size >= ND)      *((float4*)(out + off))      = v;  // z_q_st
    if (out_size >= 2 * ND)  *((float4*)(out + ND + off)) = v;  // z_q

    if (q == 0) {   // indices (as float: 0..511 exact)
        if (out_size >= 2 * ND + NROWS)      out[2 * ND + n] = (float)idx;
        else if (out_size == ND + NROWS)     out[ND + n]     = (float)idx;
        else if (out_size == NROWS)          out[n]          = (float)idx;
    }
}

// ---------------------------------------------------------------------------
extern "C" void kernel_launch(void* const* d_in, const int* in_sizes, int n_in,
                              void* d_out, int out_size) {
    const float* z   = (const float*)d_in[0];
    const float* emb = (const float*)d_in[1];
    if (n_in >= 2 && in_sizes[0] == KCB * DDIM && in_sizes[1] == NROWS * DDIM) {
        z   = (const float*)d_in[1];
        emb = (const float*)d_in[0];
    }

    const int smem_bytes = (KHALF * DDIM + KHALF) * (int)sizeof(float);  // 66560
    static int configured = -1;
    if (configured < 0) {
        cudaFuncSetAttribute(vq_partial_kernel,
                             cudaFuncAttributeMaxDynamicSharedMemorySize, smem_bytes);
        configured = 1;
    }

    vq_partial_kernel<<<GRID_A, TPB, smem_bytes>>>(z, emb);
    vq_merge_gather_kernel<<<GRID_B, TPB>>>(emb, (float*)d_out,
                                            (long long)out_size);
}

// round 5
// speedup vs baseline: 1.8393x; 1.8393x over previous
#include <cuda_runtime.h>
#include <cuda_fp16.h>
#include <cstdint>

// VectorQuantStraightThrough via warp-level HMMA (mma.sync m16n8k16 fp16),
// fp32-emulated dot with fp16 2-way splits, 3 cross terms.
//   z scaled by 2^3, e scaled by 2^15  =>  accum = 2^18 * dot  (exact scales)
//   2*dot = accum * 2^-17 (exact)  — matches reference's exact 2*dot.
//   d2 = fl( fl(z2 - 2dot) + e2 )   (replicates reference fp32 rounding)
// z2 / e2 evaluation orders are bit-identical to the round-2 kernel that
// passed with zero index flips.

#define NROWS (32 * 4096)   // 131072
#define DDIM  64
#define KCB   512
#define MT    128           // rows per CTA
#define NTILES (NROWS / MT) // 1024 CTAs
#define TPB   256

// smem byte offsets (rows padded to 72 halves = 144 B for conflict-free LDS)
#define SM_B0   0           // e-split0 [512][72] half
#define SM_B1   73728       // e-split1
#define SM_A0   147456      // z-split0 [128][72] half
#define SM_A1   165888      // z-split1
#define SM_Z32  184320      // z tile fp32 [128][64]
#define SM_E2   217088      // e2 [512] float
#define SM_Z2   219136      // z2 [128] float
#define SM_VAL0 219648      // best val half0 [128] float
#define SM_VAL1 220160
#define SM_IDX0 220672      // best idx [128] int
#define SM_IDX1 221184
#define SM_TOTAL 221696

#define TWO_DOT_SCALE (1.0f / 131072.0f)   // 2^-17

// ---- device scratch ----
__device__ __half g_b0[KCB * DDIM];
__device__ __half g_b1[KCB * DDIM];
__device__ float  g_e2[KCB];

__device__ __forceinline__ void mma16816(float* c, const uint32_t* a,
                                         const uint32_t* b) {
    asm volatile(
        "mma.sync.aligned.m16n8k16.row.col.f32.f16.f16.f32 "
        "{%0,%1,%2,%3}, {%4,%5,%6,%7}, {%8,%9}, {%0,%1,%2,%3};"
        : "+f"(c[0]), "+f"(c[1]), "+f"(c[2]), "+f"(c[3])
        : "r"(a[0]), "r"(a[1]), "r"(a[2]), "r"(a[3]), "r"(b[0]), "r"(b[1]));
}

// ---------------- prep: e-splits (scaled 2^15) + ||e||^2 ------------------
__global__ void vq_prep_kernel(const float* __restrict__ emb) {
    const int k = blockIdx.x * 128 + threadIdx.x;   // 512 codes
    const float* e = emb + k * DDIM;
    float s = 0.f;
    #pragma unroll 8
    for (int d = 0; d < DDIM; d++) {
        const float v = e[d];
        s = fmaf(v, v, s);                     // exact round-2 e2 chain order
        const float sv = v * 32768.0f;         // exact
        const __half h0 = __float2half_rn(sv);
        const float  r  = sv - __half2float(h0);
        const __half h1 = __float2half_rn(r);
        g_b0[k * DDIM + d] = h0;
        g_b1[k * DDIM + d] = h1;
    }
    g_e2[k] = s;
}

// ---------------- main kernel ---------------------------------------------
__global__ __launch_bounds__(TPB, 1)
void vq_main_kernel(const float* __restrict__ z,
                    const float* __restrict__ emb,
                    float* __restrict__ out,
                    long long out_size) {
    extern __shared__ char smem[];
    const int tid = threadIdx.x;
    const int w   = tid >> 5;
    const int l   = tid & 31;
    const int tile = blockIdx.x;

    // ---- stage z tile fp32 (coalesced) ----
    {
        const float4* src = (const float4*)(z + (size_t)tile * MT * DDIM);
        float4* dst = (float4*)(smem + SM_Z32);
        #pragma unroll
        for (int i = tid; i < MT * DDIM / 4; i += TPB) dst[i] = src[i];
    }
    // ---- stage e-splits into padded smem (16B chunks) ----
    {
        const uint4* s0 = (const uint4*)g_b0;
        const uint4* s1 = (const uint4*)g_b1;
        #pragma unroll
        for (int c = tid; c < KCB * DDIM / 8; c += TPB) {   // 4096 chunks
            const int row = c >> 3, cc = c & 7;
            *(uint4*)(smem + SM_B0 + row * 144 + cc * 16) = s0[c];
            *(uint4*)(smem + SM_B1 + row * 144 + cc * 16) = s1[c];
        }
    }
    // e2
    #pragma unroll
    for (int i = tid; i < KCB; i += TPB)
        ((float*)(smem + SM_E2))[i] = g_e2[i];
    __syncthreads();

    // ---- convert z tile to fp16 splits (scaled 2^3), padded layout ----
    {
        const float* z32 = (const float*)(smem + SM_Z32);
        #pragma unroll
        for (int e = tid; e < MT * DDIM; e += TPB) {
            const int row = e >> 6, kk = e & 63;
            const float sv = z32[e] * 8.0f;    // exact
            const __half h0 = __float2half_rn(sv);
            const float  r  = sv - __half2float(h0);
            const __half h1 = __float2half_rn(r);
            *(__half*)(smem + SM_A0 + row * 144 + kk * 2) = h0;
            *(__half*)(smem + SM_A1 + row * 144 + kk * 2) = h1;
        }
    }
    // ---- z2 per row: EXACT round-2 evaluation order ----
    if (tid < MT) {
        const float* zr = (const float*)(smem + SM_Z32) + tid * DDIM;
        float c[8];
        #pragma unroll
        for (int p = 0; p < 8; p++) {
            float s = 0.f;
            #pragma unroll
            for (int j = 0; j < 8; j++) s = fmaf(zr[p + 8 * j], zr[p + 8 * j], s);
            c[p] = s;
        }
        const float lo = __fadd_rn(__fadd_rn(c[0], c[2]), __fadd_rn(c[4], c[6]));
        const float hi = __fadd_rn(__fadd_rn(c[1], c[3]), __fadd_rn(c[5], c[7]));
        ((float*)(smem + SM_Z2))[tid] = __fadd_rn(lo, hi);
    }
    __syncthreads();

    // ---- warp partition: 4 M-slices x 2 N-halves ----
    const int mrow0 = (w & 3) * 32;        // 32 rows per warp (2 m16 frags)
    const int nhalf = w >> 2;              // 0 or 1
    const int ncol0 = nhalf * 256;         // 32 n-tiles per warp
    const int lr = l >> 2;                 // 0..7
    const int kb = (l & 3) * 2;            // 0,2,4,6

    // ---- load A fragments (held in regs): [msub][split][ktile][4] ----
    uint32_t Af[2][2][4][4];
    #pragma unroll
    for (int m = 0; m < 2; m++) {
        const int r0 = mrow0 + m * 16 + lr;
        #pragma unroll
        for (int s = 0; s < 2; s++) {
            const char* Ab = smem + (s ? SM_A1 : SM_A0);
            #pragma unroll
            for (int kt = 0; kt < 4; kt++) {
                const int k0 = kt * 16 + kb;
                Af[m][s][kt][0] = *(const uint32_t*)(Ab + r0 * 144 + k0 * 2);
                Af[m][s][kt][1] = *(const uint32_t*)(Ab + (r0 + 8) * 144 + k0 * 2);
                Af[m][s][kt][2] = *(const uint32_t*)(Ab + r0 * 144 + (k0 + 8) * 2);
                Af[m][s][kt][3] = *(const uint32_t*)(Ab + (r0 + 8) * 144 + (k0 + 8) * 2);
            }
        }
    }

    // preload z2 for this lane's 4 tracked rows
    const float* z2s = (const float*)(smem + SM_Z2);
    const float* e2s = (const float*)(smem + SM_E2);
    float z2v[2][2];
    #pragma unroll
    for (int m = 0; m < 2; m++) {
        z2v[m][0] = z2s[mrow0 + m * 16 + lr];
        z2v[m][1] = z2s[mrow0 + m * 16 + lr + 8];
    }

    float bv[2][2] = {{3.4e38f, 3.4e38f}, {3.4e38f, 3.4e38f}};
    int   bi[2][2] = {{0, 0}, {0, 0}};

    // ---- main loop: 32 n-tiles ----
    for (int j = 0; j < 32; j++) {
        const int col0 = ncol0 + j * 8;
        const int nr = col0 + lr;

        uint32_t Bf[2][4][2];
        #pragma unroll
        for (int s = 0; s < 2; s++) {
            const char* Bb = smem + (s ? SM_B1 : SM_B0);
            #pragma unroll
            for (int kt = 0; kt < 4; kt++) {
                const int k0 = kt * 16 + kb;
                Bf[s][kt][0] = *(const uint32_t*)(Bb + nr * 144 + k0 * 2);
                Bf[s][kt][1] = *(const uint32_t*)(Bb + nr * 144 + (k0 + 8) * 2);
            }
        }

        float C[2][4] = {{0.f, 0.f, 0.f, 0.f}, {0.f, 0.f, 0.f, 0.f}};
        // term a0*b1
        #pragma unroll
        for (int kt = 0; kt < 4; kt++) {
            mma16816(C[0], Af[0][0][kt], Bf[1][kt]);
            mma16816(C[1], Af[1][0][kt], Bf[1][kt]);
        }
        // term a1*b0
        #pragma unroll
        for (int kt = 0; kt < 4; kt++) {
            mma16816(C[0], Af[0][1][kt], Bf[0][kt]);
            mma16816(C[1], Af[1][1][kt], Bf[0][kt]);
        }
        // term a0*b0 (dominant, last)
        #pragma unroll
        for (int kt = 0; kt < 4; kt++) {
            mma16816(C[0], Af[0][0][kt], Bf[0][kt]);
            mma16816(C[1], Af[1][0][kt], Bf[0][kt]);
        }

        // epilogue: d2 with reference rounding, running argmin
        const int ca = col0 + kb;          // this lane's even col
        const float e2a = e2s[ca], e2b = e2s[ca + 1];
        #pragma unroll
        for (int m = 0; m < 2; m++) {
            const float d00 = __fadd_rn(__fsub_rn(z2v[m][0], C[m][0] * TWO_DOT_SCALE), e2a);
            const float d01 = __fadd_rn(__fsub_rn(z2v[m][0], C[m][1] * TWO_DOT_SCALE), e2b);
            const float d10 = __fadd_rn(__fsub_rn(z2v[m][1], C[m][2] * TWO_DOT_SCALE), e2a);
            const float d11 = __fadd_rn(__fsub_rn(z2v[m][1], C[m][3] * TWO_DOT_SCALE), e2b);
            if (d00 < bv[m][0]) { bv[m][0] = d00; bi[m][0] = ca; }
            if (d01 < bv[m][0]) { bv[m][0] = d01; bi[m][0] = ca + 1; }
            if (d10 < bv[m][1]) { bv[m][1] = d10; bi[m][1] = ca; }
            if (d11 < bv[m][1]) { bv[m][1] = d11; bi[m][1] = ca + 1; }
        }
    }

    // ---- reduce across the 4 lanes of each quad (min, lowest index on tie)
    #pragma unroll
    for (int m = 0; m < 2; m++) {
        #pragma unroll
        for (int h = 0; h < 2; h++) {
            float v = bv[m][h];
            int   i = bi[m][h];
            #pragma unroll
            for (int s = 1; s <= 2; s <<= 1) {
                const float ov = __shfl_xor_sync(0xFFFFFFFFu, v, s);
                const int   oi = __shfl_xor_sync(0xFFFFFFFFu, i, s);
                if (ov < v || (ov == v && oi < i)) { v = ov; i = oi; }
            }
            if ((l & 3) == 0) {
                const int row = mrow0 + m * 16 + lr + h * 8;
                ((float*)(smem + (nhalf ? SM_VAL1 : SM_VAL0)))[row] = v;
                ((int*)  (smem + (nhalf ? SM_IDX1 : SM_IDX0)))[row] = i;
            }
        }
    }
    __syncthreads();

    // ---- output stage: merge halves, gather emb fp32, write ----
    const float* v0s = (const float*)(smem + SM_VAL0);
    const float* v1s = (const float*)(smem + SM_VAL1);
    const int*   i0s = (const int*)(smem + SM_IDX0);
    const int*   i1s = (const int*)(smem + SM_IDX1);

    const int r  = tid >> 1;            // local row 0..127
    const int hh = tid & 1;             // half of the 64 dims
    // half0 wins ties (lower cols == first index)
    const int idx = (v1s[r] < v0s[r]) ? i1s[r] : i0s[r];

    const long long n   = (long long)tile * MT + r;
    const long long ND  = (long long)NROWS * DDIM;   // 8388608
    const float4* ev = (const float4*)(emb + (long long)idx * DDIM) + hh * 8;
    const long long off = n * DDIM + hh * 32;

    if (out_size >= ND) {
        float4* o = (float4*)(out + off);
        #pragma unroll
        for (int q = 0; q < 8; q++) o[q] = ev[q];
    }
    if (out_size >= 2 * ND) {
        float4* o = (float4*)(out + ND + off);
        #pragma unroll
        for (int q = 0; q < 8; q++) o[q] = ev[q];
    }
    if (hh == 0) {   // indices as float (0..511 exact)
        if (out_size >= 2 * ND + NROWS)      out[2 * ND + n] = (float)idx;
        else if (out_size == ND + NROWS)     out[ND + n]     = (float)idx;
        else if (out_size == NROWS)          out[n]          = (float)idx;
    }
}

// ---------------------------------------------------------------------------
extern "C" void kernel_launch(void* const* d_in, const int* in_sizes, int n_in,
                              void* d_out, int out_size) {
    const float* z   = (const float*)d_in[0];
    const float* emb = (const float*)d_in[1];
    if (n_in >= 2 && in_sizes[0] == KCB * DDIM && in_sizes[1] == NROWS * DDIM) {
        z   = (const float*)d_in[1];
        emb = (const float*)d_in[0];
    }

    static int configured = -1;
    if (configured < 0) {
        cudaFuncSetAttribute(vq_main_kernel,
                             cudaFuncAttributeMaxDynamicSharedMemorySize, SM_TOTAL);
        configured = 1;
    }

    vq_prep_kernel<<<4, 128>>>(emb);
    vq_main_kernel<<<NTILES, TPB, SM_TOTAL>>>(z, emb, (float*)d_out,
                                              (long long)out_size);
}